// round 4
// baseline (speedup 1.0000x reference)
#include <cuda_runtime.h>
#include <cuda_bf16.h>

// Fused single kernel, software-pipelined:
//   - block decodes E -> canonical Horner coefficient slots in shared
//   - coefficients hoisted to registers (warp-uniform)
//   - mainloop: prefetch next 2 rows while computing current 2 rows,
//     so DRAM latency at iteration boundaries is covered by ~340+ issue
//     cycles of FMA/MUFU work instead of being exposed.

#define ROWS 2

__global__ __launch_bounds__(256, 2)
void ExternalForcesSI_main_kernel(const float4* __restrict__ x,
                                  const float* __restrict__ t,
                                  const float* __restrict__ layer,
                                  const float* __restrict__ omegas,
                                  const float* __restrict__ ef,
                                  const int*   __restrict__ E,
                                  float2* __restrict__ out,
                                  int n) {
    __shared__ float sC1[5];
    __shared__ float sC2[25];
    __shared__ float sC3[125];
    __shared__ float sTrig[10];

    // ---- block-local decode of E -> canonical coefficient slots ----
    const int tx = threadIdx.x;
    if (tx < 55) {
        int vars[3];
        int nv = 0;
        #pragma unroll
        for (int j = 0; j < 5; j++) {
            int c = E[tx * 5 + j];
            for (int r = 0; r < c; r++) vars[nv++] = j;   // ascending
        }
        float coef = layer[tx];
        if (nv == 1)      sC1[vars[0]] = coef;
        else if (nv == 2) sC2[vars[0] * 5 + vars[1]] = coef;
        else              sC3[(vars[0] * 5 + vars[1]) * 5 + vars[2]] = coef;
    }
    if (tx >= 64 && tx < 74) sTrig[tx - 64] = layer[55 + (tx - 64)];
    __syncthreads();

    // ---- hoist coefficients into registers (broadcast LDS) ----
    float c1[5], c2[15], c3[35], ctc[5], cts[5];
    {
        int q2 = 0, q3 = 0;
        #pragma unroll
        for (int i = 0; i < 5; i++) {
            c1[i] = sC1[i];
            ctc[i] = sTrig[i];
            cts[i] = sTrig[5 + i];
            #pragma unroll
            for (int j = i; j < 5; j++) {
                c2[q2++] = sC2[i * 5 + j];
                #pragma unroll
                for (int k = j; k < 5; k++)
                    c3[q3++] = sC3[(i * 5 + j) * 5 + k];
            }
        }
    }
    const float w0 = omegas[0];
    const float w1 = omegas[1];
    const float e0 = ef[0];
    const float e1 = ef[1];

    const int stride = gridDim.x * blockDim.x;   // per-row stride
    const int tid = blockIdx.x * blockDim.x + tx;

    // ---- prologue: load first batch ----
    float v[ROWS][5];
    int   idx[ROWS];
    #pragma unroll
    for (int r = 0; r < ROWS; r++) {
        idx[r] = tid + r * stride;
        bool a = idx[r] < n;
        float4 xv = a ? x[idx[r]] : make_float4(0.f, 0.f, 0.f, 0.f);
        float  tv = a ? t[idx[r]] : 0.f;
        v[r][0] = xv.x; v[r][1] = xv.y; v[r][2] = xv.z; v[r][3] = xv.w; v[r][4] = tv;
    }

    for (int i0 = tid; i0 < n; i0 += ROWS * stride) {
        // ---- prefetch next batch FIRST (LDGs in flight during compute) ----
        float vn[ROWS][5];
        int   nidx[ROWS];
        #pragma unroll
        for (int r = 0; r < ROWS; r++) {
            nidx[r] = i0 + (ROWS + r) * stride;
            bool a = nidx[r] < n;
            float4 xv = a ? x[nidx[r]] : make_float4(0.f, 0.f, 0.f, 0.f);
            float  tv = a ? t[nidx[r]] : 0.f;
            vn[r][0] = xv.x; vn[r][1] = xv.y; vn[r][2] = xv.z; vn[r][3] = xv.w; vn[r][4] = tv;
        }

        // ---- trig: 10*ROWS independent MUFUs issue early ----
        float strig[ROWS];
        #pragma unroll
        for (int r = 0; r < ROWS; r++) {
            float ta = 0.f, tb = 0.f;
            #pragma unroll
            for (int j = 0; j < 5; j++) {
                ta = fmaf(ctc[j], __cosf(w0 * v[r][j]), ta);
                tb = fmaf(cts[j], __sinf(w1 * v[r][j]), tb);
            }
            strig[r] = ta + tb;
        }

        // ---- degree-3 Horner: 55 FMAs/row, 5 independent ui chains ----
        #pragma unroll
        for (int r = 0; r < ROWS; r++) {
            float part[5];
            int q2 = 0, q3 = 0;
            #pragma unroll
            for (int i = 0; i < 5; i++) {
                float ui = c1[i];
                #pragma unroll
                for (int j = i; j < 5; j++) {
                    float tij = c2[q2++];
                    #pragma unroll
                    for (int k = j; k < 5; k++)
                        tij = fmaf(v[r][k], c3[q3++], tij);
                    ui = fmaf(v[r][j], tij, ui);
                }
                part[i] = v[r][i] * ui;
            }
            float s = ((part[0] + part[1]) + (part[2] + part[3])) + (part[4] + strig[r]);
            if (idx[r] < n) out[idx[r]] = make_float2(s * e0, s * e1);
        }

        // ---- rotate pipeline ----
        #pragma unroll
        for (int r = 0; r < ROWS; r++) {
            idx[r] = nidx[r];
            #pragma unroll
            for (int j = 0; j < 5; j++) v[r][j] = vn[r][j];
        }
    }
}

extern "C" void kernel_launch(void* const* d_in, const int* in_sizes, int n_in,
                              void* d_out, int out_size) {
    // metadata order: x, t, layer, omegas, ext_filter, E
    const float4* x      = (const float4*)d_in[0];
    const float*  t      = (const float*)d_in[1];
    const float*  layer  = (const float*)d_in[2];
    const float*  omegas = (const float*)d_in[3];
    const float*  ef     = (const float*)d_in[4];
    const int*    E      = (const int*)d_in[5];
    float2* out = (float2*)d_out;

    const int n = in_sizes[1];  // N_DATA (element count of t)

    // 2 CTAs/SM * 148 SMs; ~13 rows/thread -> ~6.6 pipelined iterations.
    ExternalForcesSI_main_kernel<<<296, 256>>>(x, t, layer, omegas, ef, E, out, n);
}